// round 1
// baseline (speedup 1.0000x reference)
#include <cuda_runtime.h>

#define NN 20000
#define EE 640000
#define RR 65
#define FIN 128
#define HH1 64
#define HH2 32
#define BB 8192

#define OUT_RETOS  (BB*RR)            /* 532480 */
#define OUT_RETOSA (OUT_RETOS + 2*NN) /* 572480 */
#define OUT_X2O    (OUT_RETOSA + 2*NN)/* 612480 */

// ---------------- scratch (static device globals; no allocations) -------------
__device__ float g_Y[(size_t)NN * RR * HH1];        // 333 MB, reused for Y1 (N x 4160) and Y2 (N x 2080)
__device__ float g_h1O[NN * HH1];
__device__ float g_h1A[NN * HH1];
__device__ float g_h1Aa[NN * HH1];
__device__ float g_x2o[NN * HH2];
__device__ float g_x2oa[NN * HH2];
__device__ float g_x2oaa[NN * HH2];
__device__ int   g_cnt0[RR * NN];
__device__ int   g_cnt1[RR * NN];
__device__ float g_inv0[RR * NN];
__device__ float g_inv1[RR * NN];
__device__ __align__(16) float g_colsum[HH2];
__device__ __align__(16) float g_v[HH2];

// ---------------- small kernels ----------------------------------------------
__global__ void zero_k() {
    int i = blockIdx.x * blockDim.x + threadIdx.x;
    if (i < RR * NN) { g_cnt0[i] = 0; g_cnt1[i] = 0; }
    if (i < HH2) g_colsum[i] = 0.f;
}

__global__ void count_k(const int* __restrict__ ei, const int* __restrict__ et0,
                        const int* __restrict__ et1) {
    int e = blockIdx.x * blockDim.x + threadIdx.x;
    if (e >= EE) return;
    int d = ei[EE + e];
    atomicAdd(&g_cnt0[et0[e] * NN + d], 1);
    atomicAdd(&g_cnt1[et1[e] * NN + d], 1);
}

__global__ void inv_k() {
    int i = blockIdx.x * blockDim.x + threadIdx.x;
    if (i >= RR * NN) return;
    g_inv0[i] = 1.f / (float)max(g_cnt0[i], 1);
    g_inv1[i] = 1.f / (float)max(g_cnt1[i], 1);
}

__global__ void relu3_k() {
    int i = blockIdx.x * blockDim.x + threadIdx.x;
    if (i >= NN * HH1) return;
    g_h1O[i]  = fmaxf(g_h1O[i],  0.f);
    g_h1A[i]  = fmaxf(g_h1A[i],  0.f);
    g_h1Aa[i] = fmaxf(g_h1Aa[i], 0.f);
}

// ---------------- tiled GEMM: Y[:, r*H:(r+1)*H] = X @ W[r]  (+bias) -----------
// block = 64 rows x H cols for relation r = blockIdx.y. K in {128,64}.
// A tile stored transposed in smem -> conflict-free float4 reads.
template<int K, int H>
__global__ void __launch_bounds__((H/4)*16)
gemm_rel(const float* __restrict__ X, const float* __restrict__ Wm,
         const float* __restrict__ bias, float* __restrict__ Y,
         float* __restrict__ Ydup, int ldY, int nrows)
{
    constexpr int TM = 64, KC = 64;
    constexpr int DX = H / 4;          // threads along cols
    constexpr int NT = DX * 16;        // total threads
    __shared__ __align__(16) float At[KC][TM + 4];
    __shared__ __align__(16) float Bs[KC][H];

    const float* Wr = Wm + (size_t)blockIdx.y * (K * H);
    int row0 = blockIdx.x * TM;
    int tx = threadIdx.x, ty = threadIdx.y;
    int tid = ty * DX + tx;
    int c0 = tx * 4, r0 = ty * 4;
    float acc[4][4] = {};

    for (int kc = 0; kc < K; kc += KC) {
        // load A^T chunk
        for (int c = tid; c < TM * (KC / 4); c += NT) {
            int row = c / (KC / 4), kq = c % (KC / 4);
            float4 v = make_float4(0.f, 0.f, 0.f, 0.f);
            if (row0 + row < nrows)
                v = *reinterpret_cast<const float4*>(X + (size_t)(row0 + row) * K + kc + kq * 4);
            At[kq * 4 + 0][row] = v.x;
            At[kq * 4 + 1][row] = v.y;
            At[kq * 4 + 2][row] = v.z;
            At[kq * 4 + 3][row] = v.w;
        }
        // load B chunk (contiguous)
        for (int c = tid; c < KC * H / 4; c += NT)
            reinterpret_cast<float4*>(&Bs[0][0])[c] =
                reinterpret_cast<const float4*>(Wr + (size_t)kc * H)[c];
        __syncthreads();

        #pragma unroll 8
        for (int k = 0; k < KC; k++) {
            float4 a = *reinterpret_cast<const float4*>(&At[k][r0]);
            float4 b = *reinterpret_cast<const float4*>(&Bs[k][c0]);
            acc[0][0] += a.x * b.x; acc[0][1] += a.x * b.y; acc[0][2] += a.x * b.z; acc[0][3] += a.x * b.w;
            acc[1][0] += a.y * b.x; acc[1][1] += a.y * b.y; acc[1][2] += a.y * b.z; acc[1][3] += a.y * b.w;
            acc[2][0] += a.z * b.x; acc[2][1] += a.z * b.y; acc[2][2] += a.z * b.z; acc[2][3] += a.z * b.w;
            acc[3][0] += a.w * b.x; acc[3][1] += a.w * b.y; acc[3][2] += a.w * b.z; acc[3][3] += a.w * b.w;
        }
        __syncthreads();
    }

    float4 bv = make_float4(0.f, 0.f, 0.f, 0.f);
    if (bias) bv = *reinterpret_cast<const float4*>(bias + c0);
    size_t colbase = (size_t)blockIdx.y * H + c0;
    #pragma unroll
    for (int i = 0; i < 4; i++) {
        int row = row0 + r0 + i;
        if (row < nrows) {
            float4 o = make_float4(acc[i][0] + bv.x, acc[i][1] + bv.y,
                                   acc[i][2] + bv.z, acc[i][3] + bv.w);
            *reinterpret_cast<float4*>(Y + (size_t)row * ldY + colbase) = o;
            if (Ydup)
                *reinterpret_cast<float4*>(Ydup + (size_t)row * ldY + colbase) = o;
        }
    }
}

// ---------------- edge scatter: out[dst] += Y[src, et*H:+H] * inv[et,dst] -----
template<int H>
__global__ void scatter_k(const float* __restrict__ Y, int ldY,
                          const int* __restrict__ ei, const int* __restrict__ et,
                          const float* __restrict__ inv, float* __restrict__ out)
{
    constexpr int TPE = H / 4;
    int g = blockIdx.x * blockDim.x + threadIdx.x;
    int e = g / TPE, q = g % TPE;
    if (e >= EE) return;
    int s = ei[e], d = ei[EE + e], r = et[e];
    float cf = inv[r * NN + d];
    float4 y = *reinterpret_cast<const float4*>(Y + (size_t)s * ldY + r * H + q * 4);
    float4 v = make_float4(y.x * cf, y.y * cf, y.z * cf, y.w * cf);
    atomicAdd(reinterpret_cast<float4*>(out + (size_t)d * H + q * 4), v);
}

// ---------------- readout / discriminator ------------------------------------
__global__ void colsum_k() {
    __shared__ float sm[256];
    int col = threadIdx.x & 31, grp = threadIdx.x >> 5;
    float s = 0.f;
    for (int n = blockIdx.x * 8 + grp; n < NN; n += gridDim.x * 8)
        s += g_x2o[n * HH2 + col];
    sm[threadIdx.x] = s;
    __syncthreads();
    if (threadIdx.x < 32) {
        float t = 0.f;
        #pragma unroll
        for (int g2 = 0; g2 < 8; g2++) t += sm[g2 * 32 + threadIdx.x];
        atomicAdd(&g_colsum[threadIdx.x], t);
    }
}

__global__ void finalize_k(const float* __restrict__ discW) {
    __shared__ float c[HH2];
    int t = threadIdx.x;
    float m = g_colsum[t] / (float)NN;
    c[t] = 1.f / (1.f + expf(-m));
    __syncwarp();
    float v = 0.f;
    #pragma unroll
    for (int k = 0; k < HH2; k++) v += discW[t * HH2 + k] * c[k];
    g_v[t] = v;
}

__global__ void ret_k(const float* __restrict__ dbp, float* __restrict__ out) {
    int n = blockIdx.x * blockDim.x + threadIdx.x;
    if (n >= NN) return;
    float db = dbp[0];
    float d0 = 0.f, d1 = 0.f, d2 = 0.f;
    float* xo_out = out + OUT_X2O + (size_t)n * HH2;
    #pragma unroll
    for (int k = 0; k < HH2; k += 4) {
        float4 v4 = *reinterpret_cast<const float4*>(&g_v[k]);
        float4 a  = *reinterpret_cast<const float4*>(&g_x2o[n * HH2 + k]);
        float4 b  = *reinterpret_cast<const float4*>(&g_x2oa[n * HH2 + k]);
        float4 c  = *reinterpret_cast<const float4*>(&g_x2oaa[n * HH2 + k]);
        d0 += a.x * v4.x + a.y * v4.y + a.z * v4.z + a.w * v4.w;
        d1 += b.x * v4.x + b.y * v4.y + b.z * v4.z + b.w * v4.w;
        d2 += c.x * v4.x + c.y * v4.y + c.z * v4.z + c.w * v4.w;
        *reinterpret_cast<float4*>(&xo_out[k]) = a;
    }
    out[OUT_RETOS  + 2 * n]     = d0 + db;
    out[OUT_RETOS  + 2 * n + 1] = d1 + db;
    out[OUT_RETOSA + 2 * n]     = d0 + db;
    out[OUT_RETOSA + 2 * n + 1] = d2 + db;
}

// ---------------- pair classifier --------------------------------------------
__global__ void cls_k(const int* __restrict__ idx, const float* __restrict__ f1,
                      const float* __restrict__ clsW, const float* __restrict__ clsB,
                      const float* __restrict__ attt, float* __restrict__ out)
{
    __shared__ float z[448];
    int b = blockIdx.x, t = threadIdx.x;
    int i0 = idx[b], i1 = idx[BB + b];
    float a0 = attt[0], a1 = attt[1];
    for (int k = t; k < 448; k += 128) {
        float val;
        if      (k < 64)  val = a0 * g_h1O[(size_t)i0 * 64 + k];
        else if (k < 96)  val = a1 * g_x2o[(size_t)i0 * 32 + (k - 64)];
        else if (k < 224) val = f1[(size_t)i0 * 128 + (k - 96)];
        else if (k < 288) val = a0 * g_h1O[(size_t)i1 * 64 + (k - 224)];
        else if (k < 320) val = a1 * g_x2o[(size_t)i1 * 32 + (k - 288)];
        else              val = f1[(size_t)i1 * 128 + (k - 320)];
        z[k] = val;
    }
    __syncthreads();
    if (t < RR) {
        float acc = clsB[t];
        #pragma unroll 4
        for (int k = 0; k < 448; k++) acc += z[k] * clsW[k * RR + t];
        out[(size_t)b * RR + t] = acc;
    }
}

// ---------------- launcher ----------------------------------------------------
extern "C" void kernel_launch(void* const* d_in, const int* in_sizes, int n_in,
                              void* d_out, int out_size)
{
    (void)in_sizes; (void)n_in; (void)out_size;
    const float* x_o   = (const float*)d_in[0];
    const float* x_a   = (const float*)d_in[1];
    const float* f1    = (const float*)d_in[2];
    const float* W1    = (const float*)d_in[3];
    const float* root1 = (const float*)d_in[4];
    const float* b1    = (const float*)d_in[5];
    const float* W2    = (const float*)d_in[6];
    const float* root2 = (const float*)d_in[7];
    const float* b2    = (const float*)d_in[8];
    const float* attt  = (const float*)d_in[9];
    const float* discW = (const float*)d_in[10];
    const float* discb = (const float*)d_in[11];
    const float* clsW  = (const float*)d_in[12];
    const float* clsb  = (const float*)d_in[13];
    const int*   ei    = (const int*)d_in[14];
    const int*   et0   = (const int*)d_in[15];
    const int*   et1   = (const int*)d_in[16];
    const int*   idx   = (const int*)d_in[17];
    float* out = (float*)d_out;

    float *Y, *h1O, *h1A, *h1Aa, *x2o, *x2oa, *x2oaa, *inv0, *inv1;
    cudaGetSymbolAddress((void**)&Y,     g_Y);
    cudaGetSymbolAddress((void**)&h1O,   g_h1O);
    cudaGetSymbolAddress((void**)&h1A,   g_h1A);
    cudaGetSymbolAddress((void**)&h1Aa,  g_h1Aa);
    cudaGetSymbolAddress((void**)&x2o,   g_x2o);
    cudaGetSymbolAddress((void**)&x2oa,  g_x2oa);
    cudaGetSymbolAddress((void**)&x2oaa, g_x2oaa);
    cudaGetSymbolAddress((void**)&inv0,  g_inv0);
    cudaGetSymbolAddress((void**)&inv1,  g_inv1);

    const int tRN = (RR * NN + 255) / 256;
    const int gx  = (NN + 63) / 64;
    dim3 gb1(16, 16), gb2(8, 16);

    zero_k<<<tRN, 256>>>();
    count_k<<<(EE + 255) / 256, 256>>>(ei, et0, et1);
    inv_k<<<tRN, 256>>>();

    // ---- layer 1, x_o (shared by runs O and Aa) ----
    gemm_rel<FIN, HH1><<<dim3(gx, RR), gb1>>>(x_o, W1, nullptr, Y, nullptr, RR * HH1, NN);
    gemm_rel<FIN, HH1><<<dim3(gx, 1),  gb1>>>(x_o, root1, b1, h1O, h1Aa, HH1, NN);
    scatter_k<HH1><<<(EE * 16 + 255) / 256, 256>>>(Y, RR * HH1, ei, et0, inv0, h1O);
    scatter_k<HH1><<<(EE * 16 + 255) / 256, 256>>>(Y, RR * HH1, ei, et1, inv1, h1Aa);

    // ---- layer 1, x_a ----
    gemm_rel<FIN, HH1><<<dim3(gx, RR), gb1>>>(x_a, W1, nullptr, Y, nullptr, RR * HH1, NN);
    gemm_rel<FIN, HH1><<<dim3(gx, 1),  gb1>>>(x_a, root1, b1, h1A, nullptr, HH1, NN);
    scatter_k<HH1><<<(EE * 16 + 255) / 256, 256>>>(Y, RR * HH1, ei, et0, inv0, h1A);

    relu3_k<<<(NN * HH1 + 255) / 256, 256>>>();

    // ---- layer 2, run O ----
    gemm_rel<HH1, HH2><<<dim3(gx, RR), gb2>>>(h1O, W2, nullptr, Y, nullptr, RR * HH2, NN);
    gemm_rel<HH1, HH2><<<dim3(gx, 1),  gb2>>>(h1O, root2, b2, x2o, nullptr, HH2, NN);
    scatter_k<HH2><<<(EE * 8 + 255) / 256, 256>>>(Y, RR * HH2, ei, et0, inv0, x2o);

    // ---- layer 2, run A ----
    gemm_rel<HH1, HH2><<<dim3(gx, RR), gb2>>>(h1A, W2, nullptr, Y, nullptr, RR * HH2, NN);
    gemm_rel<HH1, HH2><<<dim3(gx, 1),  gb2>>>(h1A, root2, b2, x2oa, nullptr, HH2, NN);
    scatter_k<HH2><<<(EE * 8 + 255) / 256, 256>>>(Y, RR * HH2, ei, et0, inv0, x2oa);

    // ---- layer 2, run Aa ----
    gemm_rel<HH1, HH2><<<dim3(gx, RR), gb2>>>(h1Aa, W2, nullptr, Y, nullptr, RR * HH2, NN);
    gemm_rel<HH1, HH2><<<dim3(gx, 1),  gb2>>>(h1Aa, root2, b2, x2oaa, nullptr, HH2, NN);
    scatter_k<HH2><<<(EE * 8 + 255) / 256, 256>>>(Y, RR * HH2, ei, et1, inv1, x2oaa);

    // ---- readout / discriminator / outputs ----
    colsum_k<<<80, 256>>>();
    finalize_k<<<1, 32>>>(discW);
    ret_k<<<(NN + 127) / 128, 128>>>(discb, out);
    cls_k<<<BB, 128>>>(idx, f1, clsW, clsb, attt, out);
}

// round 3
// speedup vs baseline: 1.2351x; 1.2351x over previous
#include <cuda_runtime.h>
#include <cuda_bf16.h>
#include <cstdint>

#define NN 20000
#define EE 640000
#define RR 65
#define FIN 128
#define HH1 64
#define HH2 32
#define BB 8192

#define OUT_RETOS  (BB*RR)
#define OUT_RETOSA (OUT_RETOS + 2*NN)
#define OUT_X2O    (OUT_RETOSA + 2*NN)

#define RCOLS1 (RR*HH1)   /* 4160 */
#define RCOLS2 (RR*HH2)   /* 2080 */

// ---------------- scratch ------------------------------------------------------
__device__ float g_Y[(size_t)NN * RR * HH1];
__device__ float g_h1O[NN * HH1];
__device__ float g_h1A[NN * HH1];
__device__ float g_h1Aa[NN * HH1];
__device__ float g_x2o[NN * HH2];
__device__ float g_x2oa[NN * HH2];
__device__ float g_x2oaa[NN * HH2];
__device__ int   g_cnt0[RR * NN];
__device__ int   g_cnt1[RR * NN];
__device__ float g_inv0[RR * NN];
__device__ float g_inv1[RR * NN];
__device__ __align__(16) float g_colsum[HH2];
__device__ __align__(16) float g_v[HH2];

// ---------------- helpers ------------------------------------------------------
__device__ __forceinline__ uint32_t pack_bf(float a, float b) {
    __nv_bfloat162 t = __floats2bfloat162_rn(a, b);
    return *reinterpret_cast<uint32_t*>(&t);
}
__device__ __forceinline__ void mma16816(float* d, const uint32_t* a, const uint32_t* b) {
    asm volatile("mma.sync.aligned.m16n8k16.row.col.f32.bf16.bf16.f32 "
        "{%0,%1,%2,%3}, {%4,%5,%6,%7}, {%8,%9}, {%0,%1,%2,%3};"
        : "+f"(d[0]), "+f"(d[1]), "+f"(d[2]), "+f"(d[3])
        : "r"(a[0]), "r"(a[1]), "r"(a[2]), "r"(a[3]), "r"(b[0]), "r"(b[1]));
}

// ---------------- HMMA split-bf16 relation GEMM --------------------------------
// Y[m, c] = sum_k X[m,k] * W[c/H][k][c%H]; tile 128x128, full K in smem.
// smem tiles row-major bf16 with +8 padding -> conflict-free quad fragment loads.
template<int K, int H, int RCOLS>
__global__ void __launch_bounds__(256)
gemm_mma(const float* __restrict__ X, const float* __restrict__ Wm,
         float* __restrict__ Y, int nrows)
{
    extern __shared__ char sm[];
    constexpr int KP = K + 8;            // padded row (bf16 elems)
    constexpr int S32 = KP / 2;          // row stride in b32
    constexpr int TSZ = 128 * KP * 2;    // bytes per tile
    __nv_bfloat16* Ahi = reinterpret_cast<__nv_bfloat16*>(sm);
    __nv_bfloat16* Alo = reinterpret_cast<__nv_bfloat16*>(sm + TSZ);
    __nv_bfloat16* Bhi = reinterpret_cast<__nv_bfloat16*>(sm + 2 * TSZ);
    __nv_bfloat16* Blo = reinterpret_cast<__nv_bfloat16*>(sm + 3 * TSZ);

    const int tid = threadIdx.x;
    const int wid = tid >> 5, lane = tid & 31;
    const int gid = lane >> 2, tig = lane & 3;
    const int wm = wid & 1, wn = wid >> 1;     // warp grid 2 x 4 (64 x 32 tiles)
    const int m0 = blockIdx.x * 128;
    const int n0 = blockIdx.y * 128;

    // ---- A tile: X rows -> hi/lo bf16 ----
    for (int idx = tid; idx < 128 * (K / 4); idx += 256) {
        int row = idx / (K / 4);
        int kq = (idx % (K / 4)) * 4;
        float4 v = make_float4(0.f, 0.f, 0.f, 0.f);
        if (m0 + row < nrows)
            v = *reinterpret_cast<const float4*>(X + (size_t)(m0 + row) * K + kq);
        float hx = __bfloat162float(__float2bfloat16_rn(v.x));
        float hy = __bfloat162float(__float2bfloat16_rn(v.y));
        float hz = __bfloat162float(__float2bfloat16_rn(v.z));
        float hw = __bfloat162float(__float2bfloat16_rn(v.w));
        int off = row * KP + kq;
        *reinterpret_cast<uint2*>(Ahi + off) = make_uint2(pack_bf(hx, hy), pack_bf(hz, hw));
        *reinterpret_cast<uint2*>(Alo + off) =
            make_uint2(pack_bf(v.x - hx, v.y - hy), pack_bf(v.z - hz, v.w - hw));
    }
    // ---- B tile: Bs[n][k] = W[(n0+n)/H][k][(n0+n)%H] ----
    for (int idx = tid; idx < 128 * K; idx += 256) {
        int n = idx & 127;
        int k = idx >> 7;
        int c = n0 + n;
        float v = 0.f;
        if (c < RCOLS) v = Wm[(size_t)(c / H) * (K * H) + (size_t)k * H + (c % H)];
        float h = __bfloat162float(__float2bfloat16_rn(v));
        Bhi[n * KP + k] = __float2bfloat16_rn(h);
        Blo[n * KP + k] = __float2bfloat16_rn(v - h);
    }
    __syncthreads();

    const uint32_t* A32h = reinterpret_cast<const uint32_t*>(Ahi);
    const uint32_t* A32l = reinterpret_cast<const uint32_t*>(Alo);
    const uint32_t* B32h = reinterpret_cast<const uint32_t*>(Bhi);
    const uint32_t* B32l = reinterpret_cast<const uint32_t*>(Blo);

    float acc[4][4][4];
    #pragma unroll
    for (int i = 0; i < 4; i++)
        #pragma unroll
        for (int j = 0; j < 4; j++)
            #pragma unroll
            for (int q = 0; q < 4; q++) acc[i][j][q] = 0.f;

    const int arow = wm * 64 + gid;
    const int brow = wn * 32 + gid;

    for (int k2 = 0; k2 < K / 2; k2 += 8) {        // k-step of 16 bf16 = 8 b32
        uint32_t ah[4][4], al[4][4], bh[4][2], bl[4][2];
        #pragma unroll
        for (int mt = 0; mt < 4; mt++) {
            int base = (arow + mt * 16) * S32 + k2 + tig;
            ah[mt][0] = A32h[base];             al[mt][0] = A32l[base];
            ah[mt][1] = A32h[base + 8 * S32];   al[mt][1] = A32l[base + 8 * S32];
            ah[mt][2] = A32h[base + 4];         al[mt][2] = A32l[base + 4];
            ah[mt][3] = A32h[base + 8 * S32 + 4]; al[mt][3] = A32l[base + 8 * S32 + 4];
        }
        #pragma unroll
        for (int nt = 0; nt < 4; nt++) {
            int base = (brow + nt * 8) * S32 + k2 + tig;
            bh[nt][0] = B32h[base]; bh[nt][1] = B32h[base + 4];
            bl[nt][0] = B32l[base]; bl[nt][1] = B32l[base + 4];
        }
        #pragma unroll
        for (int mt = 0; mt < 4; mt++)
            #pragma unroll
            for (int nt = 0; nt < 4; nt++) {
                mma16816(acc[mt][nt], ah[mt], bh[nt]);
                mma16816(acc[mt][nt], ah[mt], bl[nt]);
                mma16816(acc[mt][nt], al[mt], bh[nt]);
            }
    }

    // ---- epilogue: fragments straight to gmem (32B sector per quad) ----
    #pragma unroll
    for (int mt = 0; mt < 4; mt++) {
        int r0 = m0 + wm * 64 + mt * 16 + gid;
        #pragma unroll
        for (int nt = 0; nt < 4; nt++) {
            int c0 = n0 + wn * 32 + nt * 8 + tig * 2;
            if (c0 < RCOLS) {
                if (r0 < nrows)
                    *reinterpret_cast<float2*>(Y + (size_t)r0 * RCOLS + c0) =
                        make_float2(acc[mt][nt][0], acc[mt][nt][1]);
                if (r0 + 8 < nrows)
                    *reinterpret_cast<float2*>(Y + (size_t)(r0 + 8) * RCOLS + c0) =
                        make_float2(acc[mt][nt][2], acc[mt][nt][3]);
            }
        }
    }
}

// ---------------- small kernels ------------------------------------------------
__global__ void zero_k() {
    int i = blockIdx.x * blockDim.x + threadIdx.x;
    if (i < RR * NN) { g_cnt0[i] = 0; g_cnt1[i] = 0; }
    if (i < HH2) g_colsum[i] = 0.f;
}
__global__ void count_k(const int* __restrict__ ei, const int* __restrict__ et0,
                        const int* __restrict__ et1) {
    int e = blockIdx.x * blockDim.x + threadIdx.x;
    if (e >= EE) return;
    int d = ei[EE + e];
    atomicAdd(&g_cnt0[et0[e] * NN + d], 1);
    atomicAdd(&g_cnt1[et1[e] * NN + d], 1);
}
__global__ void inv_k() {
    int i = blockIdx.x * blockDim.x + threadIdx.x;
    if (i >= RR * NN) return;
    g_inv0[i] = 1.f / (float)max(g_cnt0[i], 1);
    g_inv1[i] = 1.f / (float)max(g_cnt1[i], 1);
}
__global__ void relu3_k() {
    int i = blockIdx.x * blockDim.x + threadIdx.x;
    if (i >= NN * HH1) return;
    g_h1O[i]  = fmaxf(g_h1O[i],  0.f);
    g_h1A[i]  = fmaxf(g_h1A[i],  0.f);
    g_h1Aa[i] = fmaxf(g_h1Aa[i], 0.f);
}

// ---------------- root GEMM (SIMT, small) --------------------------------------
template<int K, int H>
__global__ void __launch_bounds__((H/4)*16)
gemm_rel(const float* __restrict__ X, const float* __restrict__ Wm,
         const float* __restrict__ bias, float* __restrict__ Y,
         float* __restrict__ Ydup, int ldY, int nrows)
{
    constexpr int TM = 64, KC = 64;
    constexpr int DX = H / 4;
    constexpr int NT = DX * 16;
    __shared__ __align__(16) float At[KC][TM + 4];
    __shared__ __align__(16) float Bs[KC][H];
    const float* Wr = Wm;
    int row0 = blockIdx.x * TM;
    int tx = threadIdx.x, ty = threadIdx.y;
    int tid = ty * DX + tx;
    int c0 = tx * 4, r0 = ty * 4;
    float acc[4][4] = {};
    for (int kc = 0; kc < K; kc += KC) {
        for (int c = tid; c < TM * (KC / 4); c += NT) {
            int row = c / (KC / 4), kq = c % (KC / 4);
            float4 v = make_float4(0.f, 0.f, 0.f, 0.f);
            if (row0 + row < nrows)
                v = *reinterpret_cast<const float4*>(X + (size_t)(row0 + row) * K + kc + kq * 4);
            At[kq * 4 + 0][row] = v.x; At[kq * 4 + 1][row] = v.y;
            At[kq * 4 + 2][row] = v.z; At[kq * 4 + 3][row] = v.w;
        }
        for (int c = tid; c < KC * H / 4; c += NT)
            reinterpret_cast<float4*>(&Bs[0][0])[c] =
                reinterpret_cast<const float4*>(Wr + (size_t)kc * H)[c];
        __syncthreads();
        #pragma unroll 8
        for (int k = 0; k < KC; k++) {
            float4 a = *reinterpret_cast<const float4*>(&At[k][r0]);
            float4 b = *reinterpret_cast<const float4*>(&Bs[k][c0]);
            acc[0][0] += a.x*b.x; acc[0][1] += a.x*b.y; acc[0][2] += a.x*b.z; acc[0][3] += a.x*b.w;
            acc[1][0] += a.y*b.x; acc[1][1] += a.y*b.y; acc[1][2] += a.y*b.z; acc[1][3] += a.y*b.w;
            acc[2][0] += a.z*b.x; acc[2][1] += a.z*b.y; acc[2][2] += a.z*b.z; acc[2][3] += a.z*b.w;
            acc[3][0] += a.w*b.x; acc[3][1] += a.w*b.y; acc[3][2] += a.w*b.z; acc[3][3] += a.w*b.w;
        }
        __syncthreads();
    }
    float4 bv = make_float4(0.f, 0.f, 0.f, 0.f);
    if (bias) bv = *reinterpret_cast<const float4*>(bias + c0);
    #pragma unroll
    for (int i = 0; i < 4; i++) {
        int row = row0 + r0 + i;
        if (row < nrows) {
            float4 o = make_float4(acc[i][0] + bv.x, acc[i][1] + bv.y,
                                   acc[i][2] + bv.z, acc[i][3] + bv.w);
            *reinterpret_cast<float4*>(Y + (size_t)row * ldY + c0) = o;
            if (Ydup) *reinterpret_cast<float4*>(Ydup + (size_t)row * ldY + c0) = o;
        }
    }
}

// ---------------- edge scatter --------------------------------------------------
template<int H>
__global__ void scatter_k(const float* __restrict__ Y, int ldY,
                          const int* __restrict__ ei, const int* __restrict__ et,
                          const float* __restrict__ inv, float* __restrict__ out)
{
    constexpr int TPE = H / 4;
    int g = blockIdx.x * blockDim.x + threadIdx.x;
    int e = g / TPE, q = g % TPE;
    if (e >= EE) return;
    int s = ei[e], d = ei[EE + e], r = et[e];
    float cf = inv[r * NN + d];
    float4 y = *reinterpret_cast<const float4*>(Y + (size_t)s * ldY + r * H + q * 4);
    float4 v = make_float4(y.x * cf, y.y * cf, y.z * cf, y.w * cf);
    atomicAdd(reinterpret_cast<float4*>(out + (size_t)d * H + q * 4), v);
}

// ---------------- readout / discriminator --------------------------------------
__global__ void colsum_k() {
    __shared__ float smf[256];
    int col = threadIdx.x & 31, grp = threadIdx.x >> 5;
    float s = 0.f;
    for (int n = blockIdx.x * 8 + grp; n < NN; n += gridDim.x * 8)
        s += g_x2o[n * HH2 + col];
    smf[threadIdx.x] = s;
    __syncthreads();
    if (threadIdx.x < 32) {
        float t = 0.f;
        #pragma unroll
        for (int g2 = 0; g2 < 8; g2++) t += smf[g2 * 32 + threadIdx.x];
        atomicAdd(&g_colsum[threadIdx.x], t);
    }
}
__global__ void finalize_k(const float* __restrict__ discW) {
    __shared__ float c[HH2];
    int t = threadIdx.x;
    float m = g_colsum[t] / (float)NN;
    c[t] = 1.f / (1.f + expf(-m));
    __syncwarp();
    float v = 0.f;
    #pragma unroll
    for (int k = 0; k < HH2; k++) v += discW[t * HH2 + k] * c[k];
    g_v[t] = v;
}
__global__ void ret_k(const float* __restrict__ dbp, float* __restrict__ out) {
    int n = blockIdx.x * blockDim.x + threadIdx.x;
    if (n >= NN) return;
    float db = dbp[0];
    float d0 = 0.f, d1 = 0.f, d2 = 0.f;
    float* xo_out = out + OUT_X2O + (size_t)n * HH2;
    #pragma unroll
    for (int k = 0; k < HH2; k += 4) {
        float4 v4 = *reinterpret_cast<const float4*>(&g_v[k]);
        float4 a  = *reinterpret_cast<const float4*>(&g_x2o[n * HH2 + k]);
        float4 b  = *reinterpret_cast<const float4*>(&g_x2oa[n * HH2 + k]);
        float4 c  = *reinterpret_cast<const float4*>(&g_x2oaa[n * HH2 + k]);
        d0 += a.x*v4.x + a.y*v4.y + a.z*v4.z + a.w*v4.w;
        d1 += b.x*v4.x + b.y*v4.y + b.z*v4.z + b.w*v4.w;
        d2 += c.x*v4.x + c.y*v4.y + c.z*v4.z + c.w*v4.w;
        *reinterpret_cast<float4*>(&xo_out[k]) = a;
    }
    out[OUT_RETOS  + 2 * n]     = d0 + db;
    out[OUT_RETOS  + 2 * n + 1] = d1 + db;
    out[OUT_RETOSA + 2 * n]     = d0 + db;
    out[OUT_RETOSA + 2 * n + 1] = d2 + db;
}
__global__ void cls_k(const int* __restrict__ idx, const float* __restrict__ f1,
                      const float* __restrict__ clsW, const float* __restrict__ clsB,
                      const float* __restrict__ attt, float* __restrict__ out)
{
    __shared__ float z[448];
    int b = blockIdx.x, t = threadIdx.x;
    int i0 = idx[b], i1 = idx[BB + b];
    float a0 = attt[0], a1 = attt[1];
    for (int k = t; k < 448; k += 128) {
        float val;
        if      (k < 64)  val = a0 * g_h1O[(size_t)i0 * 64 + k];
        else if (k < 96)  val = a1 * g_x2o[(size_t)i0 * 32 + (k - 64)];
        else if (k < 224) val = f1[(size_t)i0 * 128 + (k - 96)];
        else if (k < 288) val = a0 * g_h1O[(size_t)i1 * 64 + (k - 224)];
        else if (k < 320) val = a1 * g_x2o[(size_t)i1 * 32 + (k - 288)];
        else              val = f1[(size_t)i1 * 128 + (k - 320)];
        z[k] = val;
    }
    __syncthreads();
    if (t < RR) {
        float acc = clsB[t];
        #pragma unroll 4
        for (int k = 0; k < 448; k++) acc += z[k] * clsW[k * RR + t];
        out[(size_t)b * RR + t] = acc;
    }
}

// ---------------- launcher ------------------------------------------------------
extern "C" void kernel_launch(void* const* d_in, const int* in_sizes, int n_in,
                              void* d_out, int out_size)
{
    (void)in_sizes; (void)n_in; (void)out_size;
    const float* x_o   = (const float*)d_in[0];
    const float* x_a   = (const float*)d_in[1];
    const float* f1    = (const float*)d_in[2];
    const float* W1    = (const float*)d_in[3];
    const float* root1 = (const float*)d_in[4];
    const float* b1    = (const float*)d_in[5];
    const float* W2    = (const float*)d_in[6];
    const float* root2 = (const float*)d_in[7];
    const float* b2    = (const float*)d_in[8];
    const float* attt  = (const float*)d_in[9];
    const float* discW = (const float*)d_in[10];
    const float* discb = (const float*)d_in[11];
    const float* clsW  = (const float*)d_in[12];
    const float* clsb  = (const float*)d_in[13];
    const int*   ei    = (const int*)d_in[14];
    const int*   et0   = (const int*)d_in[15];
    const int*   et1   = (const int*)d_in[16];
    const int*   idx   = (const int*)d_in[17];
    float* out = (float*)d_out;

    float *Y, *h1O, *h1A, *h1Aa, *x2o, *x2oa, *x2oaa, *inv0, *inv1;
    cudaGetSymbolAddress((void**)&Y,     g_Y);
    cudaGetSymbolAddress((void**)&h1O,   g_h1O);
    cudaGetSymbolAddress((void**)&h1A,   g_h1A);
    cudaGetSymbolAddress((void**)&h1Aa,  g_h1Aa);
    cudaGetSymbolAddress((void**)&x2o,   g_x2o);
    cudaGetSymbolAddress((void**)&x2oa,  g_x2oa);
    cudaGetSymbolAddress((void**)&x2oaa, g_x2oaa);
    cudaGetSymbolAddress((void**)&inv0,  g_inv0);
    cudaGetSymbolAddress((void**)&inv1,  g_inv1);

    const int SM1 = 4 * 128 * (FIN + 8) * 2;   // 139264
    const int SM2 = 4 * 128 * (HH1 + 8) * 2;   // 73728
    cudaFuncSetAttribute(gemm_mma<FIN, HH1, RCOLS1>,
                         cudaFuncAttributeMaxDynamicSharedMemorySize, SM1);
    cudaFuncSetAttribute(gemm_mma<HH1, HH2, RCOLS2>,
                         cudaFuncAttributeMaxDynamicSharedMemorySize, SM2);

    const int tRN = (RR * NN + 255) / 256;
    const int gx  = (NN + 63) / 64;
    const int gm  = (NN + 127) / 128;            // 157
    dim3 g1(gm, (RCOLS1 + 127) / 128);           // 157 x 33
    dim3 g2(gm, (RCOLS2 + 127) / 128);           // 157 x 17
    dim3 gb1(16, 16), gb2(8, 16);

    zero_k<<<tRN, 256>>>();
    count_k<<<(EE + 255) / 256, 256>>>(ei, et0, et1);
    inv_k<<<tRN, 256>>>();

    // ---- layer 1, x_o (shared by runs O and Aa) ----
    gemm_mma<FIN, HH1, RCOLS1><<<g1, 256, SM1>>>(x_o, W1, Y, NN);
    gemm_rel<FIN, HH1><<<gx, gb1>>>(x_o, root1, b1, h1O, h1Aa, HH1, NN);
    scatter_k<HH1><<<(EE * 16 + 255) / 256, 256>>>(Y, RCOLS1, ei, et0, inv0, h1O);
    scatter_k<HH1><<<(EE * 16 + 255) / 256, 256>>>(Y, RCOLS1, ei, et1, inv1, h1Aa);

    // ---- layer 1, x_a ----
    gemm_mma<FIN, HH1, RCOLS1><<<g1, 256, SM1>>>(x_a, W1, Y, NN);
    gemm_rel<FIN, HH1><<<gx, gb1>>>(x_a, root1, b1, h1A, nullptr, HH1, NN);
    scatter_k<HH1><<<(EE * 16 + 255) / 256, 256>>>(Y, RCOLS1, ei, et0, inv0, h1A);

    relu3_k<<<(NN * HH1 + 255) / 256, 256>>>();

    // ---- layer 2, run O ----
    gemm_mma<HH1, HH2, RCOLS2><<<g2, 256, SM2>>>(h1O, W2, Y, NN);
    gemm_rel<HH1, HH2><<<gx, gb2>>>(h1O, root2, b2, x2o, nullptr, HH2, NN);
    scatter_k<HH2><<<(EE * 8 + 255) / 256, 256>>>(Y, RCOLS2, ei, et0, inv0, x2o);

    // ---- layer 2, run A ----
    gemm_mma<HH1, HH2, RCOLS2><<<g2, 256, SM2>>>(h1A, W2, Y, NN);
    gemm_rel<HH1, HH2><<<gx, gb2>>>(h1A, root2, b2, x2oa, nullptr, HH2, NN);
    scatter_k<HH2><<<(EE * 8 + 255) / 256, 256>>>(Y, RCOLS2, ei, et0, inv0, x2oa);

    // ---- layer 2, run Aa ----
    gemm_mma<HH1, HH2, RCOLS2><<<g2, 256, SM2>>>(h1Aa, W2, Y, NN);
    gemm_rel<HH1, HH2><<<gx, gb2>>>(h1Aa, root2, b2, x2oaa, nullptr, HH2, NN);
    scatter_k<HH2><<<(EE * 8 + 255) / 256, 256>>>(Y, RCOLS2, ei, et1, inv1, x2oaa);

    // ---- readout / outputs ----
    colsum_k<<<80, 256>>>();
    finalize_k<<<1, 32>>>(discW);
    ret_k<<<(NN + 127) / 128, 128>>>(discb, out);
    cls_k<<<BB, 128>>>(idx, f1, clsW, clsb, attt, out);
}

// round 4
// speedup vs baseline: 2.0437x; 1.6547x over previous
#include <cuda_runtime.h>
#include <cuda_bf16.h>
#include <cstdint>

#define NN 20000
#define EE 640000
#define RR 65
#define FIN 128
#define HH1 64
#define HH2 32
#define BB 8192

#define OUT_RETOS  (BB*RR)
#define OUT_RETOSA (OUT_RETOS + 2*NN)
#define OUT_X2O    (OUT_RETOSA + 2*NN)

#define RCOLS1 (RR*HH1)   /* 4160 */
#define RCOLS2 (RR*HH2)   /* 2080 */

// ---------------- scratch ------------------------------------------------------
__device__ float g_Y[(size_t)NN * RR * HH1];
__device__ float g_h1O[NN * HH1];
__device__ float g_h1A[NN * HH1];
__device__ float g_h1Aa[NN * HH1];
__device__ float g_x2o[NN * HH2];
__device__ float g_x2oa[NN * HH2];
__device__ float g_x2oaa[NN * HH2];
__device__ int   g_cnt0[RR * NN];
__device__ int   g_cnt1[RR * NN];
__device__ float g_inv0[RR * NN];
__device__ float g_inv1[RR * NN];
__device__ __align__(16) float g_colsum[HH2];
__device__ __align__(16) float g_v[HH2];

// bf16 hi/lo precomputed operands
__device__ __nv_bfloat16 g_xohi[NN * FIN], g_xolo[NN * FIN];
__device__ __nv_bfloat16 g_xahi[NN * FIN], g_xalo[NN * FIN];
__device__ __nv_bfloat16 g_h1Ohi[NN * HH1],  g_h1Olo[NN * HH1];
__device__ __nv_bfloat16 g_h1Ahi[NN * HH1],  g_h1Alo[NN * HH1];
__device__ __nv_bfloat16 g_h1Aahi[NN * HH1], g_h1Aalo[NN * HH1];
__device__ __nv_bfloat16 g_w1hi[RCOLS1 * FIN], g_w1lo[RCOLS1 * FIN];
__device__ __nv_bfloat16 g_w2hi[RCOLS2 * HH1], g_w2lo[RCOLS2 * HH1];

// ---------------- helpers ------------------------------------------------------
__device__ __forceinline__ uint32_t smem_u32(const void* p) {
    uint32_t a;
    asm("{ .reg .u64 t; cvta.to.shared.u64 t, %1; cvt.u32.u64 %0, t; }" : "=r"(a) : "l"(p));
    return a;
}
__device__ __forceinline__ void cp16(uint32_t dst, const void* src, int sz) {
    asm volatile("cp.async.cg.shared.global [%0], [%1], 16, %2;"
                 :: "r"(dst), "l"(src), "r"(sz) : "memory");
}
__device__ __forceinline__ void mma16816(float* d, const uint32_t* a, const uint32_t* b) {
    asm volatile("mma.sync.aligned.m16n8k16.row.col.f32.bf16.bf16.f32 "
        "{%0,%1,%2,%3}, {%4,%5,%6,%7}, {%8,%9}, {%0,%1,%2,%3};"
        : "+f"(d[0]), "+f"(d[1]), "+f"(d[2]), "+f"(d[3])
        : "r"(a[0]), "r"(a[1]), "r"(a[2]), "r"(a[3]), "r"(b[0]), "r"(b[1]));
}

// ---------------- pipelined HMMA split-bf16 GEMM -------------------------------
// Y[m, c] = sum_k A[m,k] * Bt[c,k]; A/Bt prequantized to bf16 hi/lo in gmem.
// 128x128 tile, KC=32 chunks, cp.async double buffer, 2 CTAs/SM.
template<int K, int RCOLS>
__global__ void __launch_bounds__(256, 2)
gemm_pipe(const __nv_bfloat16* __restrict__ Ahi_g, const __nv_bfloat16* __restrict__ Alo_g,
          const __nv_bfloat16* __restrict__ Bhi_g, const __nv_bfloat16* __restrict__ Blo_g,
          float* __restrict__ Y, int nrows)
{
    constexpr int KC = 32, NC = K / KC;
    constexpr int KP = KC + 8;            // 40 bf16 = 80 B padded row
    constexpr int S32 = KP / 2;           // 20
    constexpr int TILE_B = 128 * KP * 2;  // 10240 B
    extern __shared__ __align__(16) char sm[];

    const int tid = threadIdx.x;
    const int wid = tid >> 5, lane = tid & 31;
    const int gid = lane >> 2, tig = lane & 3;
    const int wm = wid & 1, wn = wid >> 1;       // 2 x 4 warp grid, 64x32 per warp
    const int m0 = blockIdx.x * 128;
    const int n0 = blockIdx.y * 128;
    const uint32_t smu = smem_u32(sm);

    float acc[4][4][4] = {};

    auto load_chunk = [&](int c, int s) {
        const int koff = c * KC;
        const uint32_t st = smu + s * (4 * TILE_B);
        #pragma unroll
        for (int j = 0; j < 8; j++) {
            int i = tid + j * 256;
            int t = i >> 9;                 // 0=Ahi 1=Alo 2=Bhi 3=Blo (warp-uniform)
            int row = (i >> 2) & 127;
            int ch = i & 3;
            const __nv_bfloat16* src;
            int sz, rg;
            if (t < 2) {
                rg = m0 + row;
                sz = (rg < nrows) ? 16 : 0;
                if (!sz) rg = 0;
                src = (t == 0 ? Ahi_g : Alo_g) + (size_t)rg * K + koff + ch * 8;
            } else {
                rg = n0 + row;
                sz = (rg < RCOLS) ? 16 : 0;
                if (!sz) rg = 0;
                src = (t == 2 ? Bhi_g : Blo_g) + (size_t)rg * K + koff + ch * 8;
            }
            cp16(st + t * TILE_B + row * 80 + ch * 16, src, sz);
        }
        asm volatile("cp.async.commit_group;" ::: "memory");
    };

    auto compute = [&](int s) {
        const char* base = sm + s * (4 * TILE_B);
        const uint32_t* A32h = reinterpret_cast<const uint32_t*>(base);
        const uint32_t* A32l = reinterpret_cast<const uint32_t*>(base + TILE_B);
        const uint32_t* B32h = reinterpret_cast<const uint32_t*>(base + 2 * TILE_B);
        const uint32_t* B32l = reinterpret_cast<const uint32_t*>(base + 3 * TILE_B);
        const int arow = wm * 64 + gid, brow = wn * 32 + gid;
        #pragma unroll
        for (int ks = 0; ks < KC / 16; ks++) {
            int k2 = ks * 8;
            uint32_t ah[4][4], al[4][4], bh[4][2], bl[4][2];
            #pragma unroll
            for (int mt = 0; mt < 4; mt++) {
                int b = (arow + mt * 16) * S32 + k2 + tig;
                ah[mt][0] = A32h[b];                al[mt][0] = A32l[b];
                ah[mt][1] = A32h[b + 8 * S32];      al[mt][1] = A32l[b + 8 * S32];
                ah[mt][2] = A32h[b + 4];            al[mt][2] = A32l[b + 4];
                ah[mt][3] = A32h[b + 8 * S32 + 4];  al[mt][3] = A32l[b + 8 * S32 + 4];
            }
            #pragma unroll
            for (int nt = 0; nt < 4; nt++) {
                int b = (brow + nt * 8) * S32 + k2 + tig;
                bh[nt][0] = B32h[b]; bh[nt][1] = B32h[b + 4];
                bl[nt][0] = B32l[b]; bl[nt][1] = B32l[b + 4];
            }
            #pragma unroll
            for (int mt = 0; mt < 4; mt++)
                #pragma unroll
                for (int nt = 0; nt < 4; nt++) {
                    mma16816(acc[mt][nt], ah[mt], bh[nt]);
                    mma16816(acc[mt][nt], ah[mt], bl[nt]);
                    mma16816(acc[mt][nt], al[mt], bh[nt]);
                }
        }
    };

    load_chunk(0, 0);
    #pragma unroll
    for (int c = 0; c < NC; c++) {
        if (c + 1 < NC) {
            load_chunk(c + 1, (c + 1) & 1);
            asm volatile("cp.async.wait_group 1;" ::: "memory");
        } else {
            asm volatile("cp.async.wait_group 0;" ::: "memory");
        }
        __syncthreads();
        compute(c & 1);
        __syncthreads();
    }

    // ---- epilogue: fragments straight to gmem ----
    #pragma unroll
    for (int mt = 0; mt < 4; mt++) {
        int r0 = m0 + wm * 64 + mt * 16 + gid;
        #pragma unroll
        for (int nt = 0; nt < 4; nt++) {
            int c0 = n0 + wn * 32 + nt * 8 + tig * 2;
            if (c0 < RCOLS) {
                if (r0 < nrows)
                    *reinterpret_cast<float2*>(Y + (size_t)r0 * RCOLS + c0) =
                        make_float2(acc[mt][nt][0], acc[mt][nt][1]);
                if (r0 + 8 < nrows)
                    *reinterpret_cast<float2*>(Y + (size_t)(r0 + 8) * RCOLS + c0) =
                        make_float2(acc[mt][nt][2], acc[mt][nt][3]);
            }
        }
    }
}

// ---------------- conversion kernels -------------------------------------------
__global__ void convX_k(const float* __restrict__ X, __nv_bfloat16* __restrict__ hi,
                        __nv_bfloat16* __restrict__ lo, int n) {
    int i = blockIdx.x * blockDim.x + threadIdx.x;
    if (i >= n) return;
    float v = X[i];
    __nv_bfloat16 h = __float2bfloat16_rn(v);
    hi[i] = h;
    lo[i] = __float2bfloat16_rn(v - __bfloat162float(h));
}

template<int K, int H>
__global__ void convW_k(const float* __restrict__ W, __nv_bfloat16* __restrict__ hi,
                        __nv_bfloat16* __restrict__ lo, int rcols) {
    int i = blockIdx.x * blockDim.x + threadIdx.x;
    if (i >= rcols * K) return;
    int c = i / K, k = i % K;
    float v = W[(size_t)(c / H) * (K * H) + (size_t)k * H + (c % H)];
    __nv_bfloat16 h = __float2bfloat16_rn(v);
    hi[i] = h;
    lo[i] = __float2bfloat16_rn(v - __bfloat162float(h));
}

__global__ void relu_conv_k() {
    int i = blockIdx.x * blockDim.x + threadIdx.x;
    if (i >= NN * HH1) return;
    float a = fmaxf(g_h1O[i], 0.f);  g_h1O[i] = a;
    __nv_bfloat16 h = __float2bfloat16_rn(a);
    g_h1Ohi[i] = h;  g_h1Olo[i] = __float2bfloat16_rn(a - __bfloat162float(h));
    float b = fmaxf(g_h1A[i], 0.f);  g_h1A[i] = b;
    h = __float2bfloat16_rn(b);
    g_h1Ahi[i] = h;  g_h1Alo[i] = __float2bfloat16_rn(b - __bfloat162float(h));
    float c = fmaxf(g_h1Aa[i], 0.f); g_h1Aa[i] = c;
    h = __float2bfloat16_rn(c);
    g_h1Aahi[i] = h; g_h1Aalo[i] = __float2bfloat16_rn(c - __bfloat162float(h));
}

// ---------------- small kernels ------------------------------------------------
__global__ void zero_k() {
    int i = blockIdx.x * blockDim.x + threadIdx.x;
    if (i < RR * NN) { g_cnt0[i] = 0; g_cnt1[i] = 0; }
    if (i < HH2) g_colsum[i] = 0.f;
}
__global__ void count_k(const int* __restrict__ ei, const int* __restrict__ et0,
                        const int* __restrict__ et1) {
    int e = blockIdx.x * blockDim.x + threadIdx.x;
    if (e >= EE) return;
    int d = ei[EE + e];
    atomicAdd(&g_cnt0[et0[e] * NN + d], 1);
    atomicAdd(&g_cnt1[et1[e] * NN + d], 1);
}
__global__ void inv_k() {
    int i = blockIdx.x * blockDim.x + threadIdx.x;
    if (i >= RR * NN) return;
    g_inv0[i] = 1.f / (float)max(g_cnt0[i], 1);
    g_inv1[i] = 1.f / (float)max(g_cnt1[i], 1);
}

// ---------------- root GEMM (SIMT, small) --------------------------------------
template<int K, int H>
__global__ void __launch_bounds__((H/4)*16)
gemm_rel(const float* __restrict__ X, const float* __restrict__ Wm,
         const float* __restrict__ bias, float* __restrict__ Y,
         float* __restrict__ Ydup, int ldY, int nrows)
{
    constexpr int TM = 64, KC = 64;
    constexpr int DX = H / 4;
    constexpr int NT = DX * 16;
    __shared__ __align__(16) float At[KC][TM + 4];
    __shared__ __align__(16) float Bs[KC][H];
    int row0 = blockIdx.x * TM;
    int tx = threadIdx.x, ty = threadIdx.y;
    int tid = ty * DX + tx;
    int c0 = tx * 4, r0 = ty * 4;
    float acc[4][4] = {};
    for (int kc = 0; kc < K; kc += KC) {
        for (int c = tid; c < TM * (KC / 4); c += NT) {
            int row = c / (KC / 4), kq = c % (KC / 4);
            float4 v = make_float4(0.f, 0.f, 0.f, 0.f);
            if (row0 + row < nrows)
                v = *reinterpret_cast<const float4*>(X + (size_t)(row0 + row) * K + kc + kq * 4);
            At[kq * 4 + 0][row] = v.x; At[kq * 4 + 1][row] = v.y;
            At[kq * 4 + 2][row] = v.z; At[kq * 4 + 3][row] = v.w;
        }
        for (int c = tid; c < KC * H / 4; c += NT)
            reinterpret_cast<float4*>(&Bs[0][0])[c] =
                reinterpret_cast<const float4*>(Wm + (size_t)kc * H)[c];
        __syncthreads();
        #pragma unroll 8
        for (int k = 0; k < KC; k++) {
            float4 a = *reinterpret_cast<const float4*>(&At[k][r0]);
            float4 b = *reinterpret_cast<const float4*>(&Bs[k][c0]);
            acc[0][0] += a.x*b.x; acc[0][1] += a.x*b.y; acc[0][2] += a.x*b.z; acc[0][3] += a.x*b.w;
            acc[1][0] += a.y*b.x; acc[1][1] += a.y*b.y; acc[1][2] += a.y*b.z; acc[1][3] += a.y*b.w;
            acc[2][0] += a.z*b.x; acc[2][1] += a.z*b.y; acc[2][2] += a.z*b.z; acc[2][3] += a.z*b.w;
            acc[3][0] += a.w*b.x; acc[3][1] += a.w*b.y; acc[3][2] += a.w*b.z; acc[3][3] += a.w*b.w;
        }
        __syncthreads();
    }
    float4 bv = make_float4(0.f, 0.f, 0.f, 0.f);
    if (bias) bv = *reinterpret_cast<const float4*>(bias + c0);
    #pragma unroll
    for (int i = 0; i < 4; i++) {
        int row = row0 + r0 + i;
        if (row < nrows) {
            float4 o = make_float4(acc[i][0] + bv.x, acc[i][1] + bv.y,
                                   acc[i][2] + bv.z, acc[i][3] + bv.w);
            *reinterpret_cast<float4*>(Y + (size_t)row * ldY + c0) = o;
            if (Ydup) *reinterpret_cast<float4*>(Ydup + (size_t)row * ldY + c0) = o;
        }
    }
}

// ---------------- edge scatter --------------------------------------------------
template<int H>
__global__ void scatter_k(const float* __restrict__ Y, int ldY,
                          const int* __restrict__ ei, const int* __restrict__ et,
                          const float* __restrict__ inv, float* __restrict__ out)
{
    constexpr int TPE = H / 4;
    int g = blockIdx.x * blockDim.x + threadIdx.x;
    int e = g / TPE, q = g % TPE;
    if (e >= EE) return;
    int s = ei[e], d = ei[EE + e], r = et[e];
    float cf = inv[r * NN + d];
    float4 y = *reinterpret_cast<const float4*>(Y + (size_t)s * ldY + r * H + q * 4);
    float4 v = make_float4(y.x * cf, y.y * cf, y.z * cf, y.w * cf);
    atomicAdd(reinterpret_cast<float4*>(out + (size_t)d * H + q * 4), v);
}

// ---------------- readout / discriminator --------------------------------------
__global__ void colsum_k() {
    __shared__ float smf[256];
    int col = threadIdx.x & 31, grp = threadIdx.x >> 5;
    float s = 0.f;
    for (int n = blockIdx.x * 8 + grp; n < NN; n += gridDim.x * 8)
        s += g_x2o[n * HH2 + col];
    smf[threadIdx.x] = s;
    __syncthreads();
    if (threadIdx.x < 32) {
        float t = 0.f;
        #pragma unroll
        for (int g2 = 0; g2 < 8; g2++) t += smf[g2 * 32 + threadIdx.x];
        atomicAdd(&g_colsum[threadIdx.x], t);
    }
}
__global__ void finalize_k(const float* __restrict__ discW) {
    __shared__ float c[HH2];
    int t = threadIdx.x;
    float m = g_colsum[t] / (float)NN;
    c[t] = 1.f / (1.f + expf(-m));
    __syncwarp();
    float v = 0.f;
    #pragma unroll
    for (int k = 0; k < HH2; k++) v += discW[t * HH2 + k] * c[k];
    g_v[t] = v;
}
__global__ void ret_k(const float* __restrict__ dbp, float* __restrict__ out) {
    int n = blockIdx.x * blockDim.x + threadIdx.x;
    if (n >= NN) return;
    float db = dbp[0];
    float d0 = 0.f, d1 = 0.f, d2 = 0.f;
    float* xo_out = out + OUT_X2O + (size_t)n * HH2;
    #pragma unroll
    for (int k = 0; k < HH2; k += 4) {
        float4 v4 = *reinterpret_cast<const float4*>(&g_v[k]);
        float4 a  = *reinterpret_cast<const float4*>(&g_x2o[n * HH2 + k]);
        float4 b  = *reinterpret_cast<const float4*>(&g_x2oa[n * HH2 + k]);
        float4 c  = *reinterpret_cast<const float4*>(&g_x2oaa[n * HH2 + k]);
        d0 += a.x*v4.x + a.y*v4.y + a.z*v4.z + a.w*v4.w;
        d1 += b.x*v4.x + b.y*v4.y + b.z*v4.z + b.w*v4.w;
        d2 += c.x*v4.x + c.y*v4.y + c.z*v4.z + c.w*v4.w;
        *reinterpret_cast<float4*>(&xo_out[k]) = a;
    }
    out[OUT_RETOS  + 2 * n]     = d0 + db;
    out[OUT_RETOS  + 2 * n + 1] = d1 + db;
    out[OUT_RETOSA + 2 * n]     = d0 + db;
    out[OUT_RETOSA + 2 * n + 1] = d2 + db;
}
__global__ void cls_k(const int* __restrict__ idx, const float* __restrict__ f1,
                      const float* __restrict__ clsW, const float* __restrict__ clsB,
                      const float* __restrict__ attt, float* __restrict__ out)
{
    __shared__ float z[448];
    int b = blockIdx.x, t = threadIdx.x;
    int i0 = idx[b], i1 = idx[BB + b];
    float a0 = attt[0], a1 = attt[1];
    for (int k = t; k < 448; k += 128) {
        float val;
        if      (k < 64)  val = a0 * g_h1O[(size_t)i0 * 64 + k];
        else if (k < 96)  val = a1 * g_x2o[(size_t)i0 * 32 + (k - 64)];
        else if (k < 224) val = f1[(size_t)i0 * 128 + (k - 96)];
        else if (k < 288) val = a0 * g_h1O[(size_t)i1 * 64 + (k - 224)];
        else if (k < 320) val = a1 * g_x2o[(size_t)i1 * 32 + (k - 288)];
        else              val = f1[(size_t)i1 * 128 + (k - 320)];
        z[k] = val;
    }
    __syncthreads();
    if (t < RR) {
        float acc = clsB[t];
        #pragma unroll 4
        for (int k = 0; k < 448; k++) acc += z[k] * clsW[k * RR + t];
        out[(size_t)b * RR + t] = acc;
    }
}

// ---------------- launcher ------------------------------------------------------
extern "C" void kernel_launch(void* const* d_in, const int* in_sizes, int n_in,
                              void* d_out, int out_size)
{
    (void)in_sizes; (void)n_in; (void)out_size;
    const float* x_o   = (const float*)d_in[0];
    const float* x_a   = (const float*)d_in[1];
    const float* f1    = (const float*)d_in[2];
    const float* W1    = (const float*)d_in[3];
    const float* root1 = (const float*)d_in[4];
    const float* b1    = (const float*)d_in[5];
    const float* W2    = (const float*)d_in[6];
    const float* root2 = (const float*)d_in[7];
    const float* b2    = (const float*)d_in[8];
    const float* attt  = (const float*)d_in[9];
    const float* discW = (const float*)d_in[10];
    const float* discb = (const float*)d_in[11];
    const float* clsW  = (const float*)d_in[12];
    const float* clsb  = (const float*)d_in[13];
    const int*   ei    = (const int*)d_in[14];
    const int*   et0   = (const int*)d_in[15];
    const int*   et1   = (const int*)d_in[16];
    const int*   idx   = (const int*)d_in[17];
    float* out = (float*)d_out;

    float *Y, *h1O, *h1A, *h1Aa, *x2o, *x2oa, *x2oaa, *inv0, *inv1;
    cudaGetSymbolAddress((void**)&Y,     g_Y);
    cudaGetSymbolAddress((void**)&h1O,   g_h1O);
    cudaGetSymbolAddress((void**)&h1A,   g_h1A);
    cudaGetSymbolAddress((void**)&h1Aa,  g_h1Aa);
    cudaGetSymbolAddress((void**)&x2o,   g_x2o);
    cudaGetSymbolAddress((void**)&x2oa,  g_x2oa);
    cudaGetSymbolAddress((void**)&x2oaa, g_x2oaa);
    cudaGetSymbolAddress((void**)&inv0,  g_inv0);
    cudaGetSymbolAddress((void**)&inv1,  g_inv1);

    __nv_bfloat16 *xohi,*xolo,*xahi,*xalo,*w1hi,*w1lo,*w2hi,*w2lo;
    __nv_bfloat16 *h1Ohi,*h1Olo,*h1Ahi,*h1Alo,*h1Aahi,*h1Aalo;
    cudaGetSymbolAddress((void**)&xohi, g_xohi);   cudaGetSymbolAddress((void**)&xolo, g_xolo);
    cudaGetSymbolAddress((void**)&xahi, g_xahi);   cudaGetSymbolAddress((void**)&xalo, g_xalo);
    cudaGetSymbolAddress((void**)&w1hi, g_w1hi);   cudaGetSymbolAddress((void**)&w1lo, g_w1lo);
    cudaGetSymbolAddress((void**)&w2hi, g_w2hi);   cudaGetSymbolAddress((void**)&w2lo, g_w2lo);
    cudaGetSymbolAddress((void**)&h1Ohi, g_h1Ohi); cudaGetSymbolAddress((void**)&h1Olo, g_h1Olo);
    cudaGetSymbolAddress((void**)&h1Ahi, g_h1Ahi); cudaGetSymbolAddress((void**)&h1Alo, g_h1Alo);
    cudaGetSymbolAddress((void**)&h1Aahi, g_h1Aahi); cudaGetSymbolAddress((void**)&h1Aalo, g_h1Aalo);

    const int SMP = 2 * 4 * 128 * 40 * 2;   // 81920
    cudaFuncSetAttribute(gemm_pipe<FIN, RCOLS1>,
                         cudaFuncAttributeMaxDynamicSharedMemorySize, SMP);
    cudaFuncSetAttribute(gemm_pipe<HH1, RCOLS2>,
                         cudaFuncAttributeMaxDynamicSharedMemorySize, SMP);

    const int tRN = (RR * NN + 255) / 256;
    const int gx  = (NN + 63) / 64;
    const int gm  = (NN + 127) / 128;            // 157
    dim3 g1(gm, (RCOLS1 + 127) / 128);           // 157 x 33
    dim3 g2(gm, (RCOLS2 + 127) / 128);           // 157 x 17
    dim3 gb1(16, 16), gb2(8, 16);

    zero_k<<<tRN, 256>>>();
    count_k<<<(EE + 255) / 256, 256>>>(ei, et0, et1);
    inv_k<<<tRN, 256>>>();

    // ---- precompute bf16 hi/lo operands ----
    convX_k<<<(NN * FIN + 255) / 256, 256>>>(x_o, xohi, xolo, NN * FIN);
    convX_k<<<(NN * FIN + 255) / 256, 256>>>(x_a, xahi, xalo, NN * FIN);
    convW_k<FIN, HH1><<<(RCOLS1 * FIN + 255) / 256, 256>>>(W1, w1hi, w1lo, RCOLS1);
    convW_k<HH1, HH2><<<(RCOLS2 * HH1 + 255) / 256, 256>>>(W2, w2hi, w2lo, RCOLS2);

    // ---- layer 1, x_o (shared by runs O and Aa) ----
    gemm_pipe<FIN, RCOLS1><<<g1, 256, SMP>>>(xohi, xolo, w1hi, w1lo, Y, NN);
    gemm_rel<FIN, HH1><<<gx, gb1>>>(x_o, root1, b1, h1O, h1Aa, HH1, NN);
    scatter_k<HH1><<<(EE * 16 + 255) / 256, 256>>>(Y, RCOLS1, ei, et0, inv0, h1O);
    scatter_k<HH1><<<(EE * 16 + 255) / 256, 256>>>(Y, RCOLS1, ei, et1, inv1, h1Aa);

    // ---- layer 1, x_a ----
    gemm_pipe<FIN, RCOLS1><<<g1, 256, SMP>>>(xahi, xalo, w1hi, w1lo, Y, NN);
    gemm_rel<FIN, HH1><<<gx, gb1>>>(x_a, root1, b1, h1A, nullptr, HH1, NN);
    scatter_k<HH1><<<(EE * 16 + 255) / 256, 256>>>(Y, RCOLS1, ei, et0, inv0, h1A);

    relu_conv_k<<<(NN * HH1 + 255) / 256, 256>>>();

    // ---- layer 2, run O ----
    gemm_pipe<HH1, RCOLS2><<<g2, 256, SMP>>>(h1Ohi, h1Olo, w2hi, w2lo, Y, NN);
    gemm_rel<HH1, HH2><<<gx, gb2>>>(h1O, root2, b2, x2o, nullptr, HH2, NN);
    scatter_k<HH2><<<(EE * 8 + 255) / 256, 256>>>(Y, RCOLS2, ei, et0, inv0, x2o);

    // ---- layer 2, run A ----
    gemm_pipe<HH1, RCOLS2><<<g2, 256, SMP>>>(h1Ahi, h1Alo, w2hi, w2lo, Y, NN);
    gemm_rel<HH1, HH2><<<gx, gb2>>>(h1A, root2, b2, x2oa, nullptr, HH2, NN);
    scatter_k<HH2><<<(EE * 8 + 255) / 256, 256>>>(Y, RCOLS2, ei, et0, inv0, x2oa);

    // ---- layer 2, run Aa ----
    gemm_pipe<HH1, RCOLS2><<<g2, 256, SMP>>>(h1Aahi, h1Aalo, w2hi, w2lo, Y, NN);
    gemm_rel<HH1, HH2><<<gx, gb2>>>(h1Aa, root2, b2, x2oaa, nullptr, HH2, NN);
    scatter_k<HH2><<<(EE * 8 + 255) / 256, 256>>>(Y, RCOLS2, ei, et1, inv1, x2oaa);

    // ---- readout / outputs ----
    colsum_k<<<80, 256>>>();
    finalize_k<<<1, 32>>>(discW);
    ret_k<<<(NN + 127) / 128, 128>>>(discb, out);
    cls_k<<<BB, 128>>>(idx, f1, clsW, clsb, attt, out);
}

// round 5
// speedup vs baseline: 2.3802x; 1.1646x over previous
#include <cuda_runtime.h>
#include <cuda_bf16.h>
#include <cstdint>

#define NN 20000
#define EE 640000
#define RR 65
#define FIN 128
#define HH1 64
#define HH2 32
#define BB 8192
#define KEYS (RR*NN)          /* 1,300,000 */
#define NBLK ((KEYS + 1023) / 1024)

#define OUT_RETOS  (BB*RR)
#define OUT_RETOSA (OUT_RETOS + 2*NN)
#define OUT_X2O    (OUT_RETOSA + 2*NN)

#define RCOLS1 (RR*HH1)   /* 4160 */
#define RCOLS2 (RR*HH2)   /* 2080 */

// ---------------- scratch ------------------------------------------------------
__device__ float g_h1O[NN * HH1];
__device__ float g_h1A[NN * HH1];
__device__ float g_h1Aa[NN * HH1];
__device__ float g_x2o[NN * HH2];
__device__ float g_x2oa[NN * HH2];
__device__ float g_x2oaa[NN * HH2];
__device__ int   g_cnt0[KEYS];
__device__ int   g_cnt1[KEYS];
__device__ float g_inv0[KEYS];
__device__ float g_inv1[KEYS];
__device__ __align__(16) float g_colsum[HH2];
__device__ __align__(16) float g_v[HH2];

// CSR by (etype * NN + src)
__device__ int  g_hist0[KEYS], g_hist1[KEYS];
__device__ int  g_off0[KEYS + 1], g_off1[KEYS + 1];
__device__ int  g_cur0[KEYS], g_cur1[KEYS];
__device__ int2 g_sd0[EE], g_sd1[EE];
__device__ float g_sc0[EE], g_sc1[EE];
__device__ int  g_blk0[NBLK + 1], g_blk1[NBLK + 1];

// bf16 hi/lo precomputed operands
__device__ __nv_bfloat16 g_xohi[NN * FIN], g_xolo[NN * FIN];
__device__ __nv_bfloat16 g_xahi[NN * FIN], g_xalo[NN * FIN];
__device__ __nv_bfloat16 g_h1Ohi[NN * HH1],  g_h1Olo[NN * HH1];
__device__ __nv_bfloat16 g_h1Ahi[NN * HH1],  g_h1Alo[NN * HH1];
__device__ __nv_bfloat16 g_h1Aahi[NN * HH1], g_h1Aalo[NN * HH1];
__device__ __nv_bfloat16 g_w1hi[RCOLS1 * FIN], g_w1lo[RCOLS1 * FIN];
__device__ __nv_bfloat16 g_w2hi[RCOLS2 * HH1], g_w2lo[RCOLS2 * HH1];

// ---------------- helpers ------------------------------------------------------
__device__ __forceinline__ uint32_t smem_u32(const void* p) {
    uint32_t a;
    asm("{ .reg .u64 t; cvta.to.shared.u64 t, %1; cvt.u32.u64 %0, t; }" : "=r"(a) : "l"(p));
    return a;
}
__device__ __forceinline__ void cp16(uint32_t dst, const void* src, int sz) {
    asm volatile("cp.async.cg.shared.global [%0], [%1], 16, %2;"
                 :: "r"(dst), "l"(src), "r"(sz) : "memory");
}
__device__ __forceinline__ void mma16816(float* d, const uint32_t* a, const uint32_t* b) {
    asm volatile("mma.sync.aligned.m16n8k16.row.col.f32.bf16.bf16.f32 "
        "{%0,%1,%2,%3}, {%4,%5,%6,%7}, {%8,%9}, {%0,%1,%2,%3};"
        : "+f"(d[0]), "+f"(d[1]), "+f"(d[2]), "+f"(d[3])
        : "r"(a[0]), "r"(a[1]), "r"(a[2]), "r"(a[3]), "r"(b[0]), "r"(b[1]));
}

// ---------------- fused GEMM + edge scatter ------------------------------------
template<int K, int H, int RCOLS>
__global__ void __launch_bounds__(256, 2)
gemm_fused(const __nv_bfloat16* __restrict__ Ahi_g, const __nv_bfloat16* __restrict__ Alo_g,
           const __nv_bfloat16* __restrict__ Bhi_g, const __nv_bfloat16* __restrict__ Blo_g,
           const int* __restrict__ off0, const int2* __restrict__ sd0,
           const float* __restrict__ sc0, float* __restrict__ out0,
           const int* __restrict__ off1, const int2* __restrict__ sd1,
           const float* __restrict__ sc1, float* __restrict__ out1,
           int nrows)
{
    constexpr int KC = 32, NC = K / KC;
    constexpr int KP = KC + 8;
    constexpr int S32 = KP / 2;
    constexpr int TILE_B = 128 * KP * 2;
    extern __shared__ __align__(16) char sm[];

    const int tid = threadIdx.x;
    const int wid = tid >> 5, lane = tid & 31;
    const int gid = lane >> 2, tig = lane & 3;
    const int wm = wid & 1, wn = wid >> 1;
    const int m0 = blockIdx.x * 128;
    const int n0 = blockIdx.y * 128;
    const uint32_t smu = smem_u32(sm);

    float acc[4][4][4] = {};

    auto load_chunk = [&](int c, int s) {
        const int koff = c * KC;
        const uint32_t st = smu + s * (4 * TILE_B);
        #pragma unroll
        for (int j = 0; j < 8; j++) {
            int i = tid + j * 256;
            int t = i >> 9;
            int row = (i >> 2) & 127;
            int ch = i & 3;
            const __nv_bfloat16* src;
            int sz, rg;
            if (t < 2) {
                rg = m0 + row;
                sz = (rg < nrows) ? 16 : 0;
                if (!sz) rg = 0;
                src = (t == 0 ? Ahi_g : Alo_g) + (size_t)rg * K + koff + ch * 8;
            } else {
                rg = n0 + row;
                sz = (rg < RCOLS) ? 16 : 0;
                if (!sz) rg = 0;
                src = (t == 2 ? Bhi_g : Blo_g) + (size_t)rg * K + koff + ch * 8;
            }
            cp16(st + t * TILE_B + row * 80 + ch * 16, src, sz);
        }
        asm volatile("cp.async.commit_group;" ::: "memory");
    };

    auto compute = [&](int s) {
        const char* base = sm + s * (4 * TILE_B);
        const uint32_t* A32h = reinterpret_cast<const uint32_t*>(base);
        const uint32_t* A32l = reinterpret_cast<const uint32_t*>(base + TILE_B);
        const uint32_t* B32h = reinterpret_cast<const uint32_t*>(base + 2 * TILE_B);
        const uint32_t* B32l = reinterpret_cast<const uint32_t*>(base + 3 * TILE_B);
        const int arow = wm * 64 + gid, brow = wn * 32 + gid;
        #pragma unroll
        for (int ks = 0; ks < KC / 16; ks++) {
            int k2 = ks * 8;
            uint32_t ah[4][4], al[4][4], bh[4][2], bl[4][2];
            #pragma unroll
            for (int mt = 0; mt < 4; mt++) {
                int b = (arow + mt * 16) * S32 + k2 + tig;
                ah[mt][0] = A32h[b];                al[mt][0] = A32l[b];
                ah[mt][1] = A32h[b + 8 * S32];      al[mt][1] = A32l[b + 8 * S32];
                ah[mt][2] = A32h[b + 4];            al[mt][2] = A32l[b + 4];
                ah[mt][3] = A32h[b + 8 * S32 + 4];  al[mt][3] = A32l[b + 8 * S32 + 4];
            }
            #pragma unroll
            for (int nt = 0; nt < 4; nt++) {
                int b = (brow + nt * 8) * S32 + k2 + tig;
                bh[nt][0] = B32h[b]; bh[nt][1] = B32h[b + 4];
                bl[nt][0] = B32l[b]; bl[nt][1] = B32l[b + 4];
            }
            #pragma unroll
            for (int mt = 0; mt < 4; mt++)
                #pragma unroll
                for (int nt = 0; nt < 4; nt++) {
                    mma16816(acc[mt][nt], ah[mt], bh[nt]);
                    mma16816(acc[mt][nt], ah[mt], bl[nt]);
                    mma16816(acc[mt][nt], al[mt], bh[nt]);
                }
        }
    };

    load_chunk(0, 0);
    #pragma unroll
    for (int c = 0; c < NC; c++) {
        if (c + 1 < NC) {
            load_chunk(c + 1, (c + 1) & 1);
            asm volatile("cp.async.wait_group 1;" ::: "memory");
        } else {
            asm volatile("cp.async.wait_group 0;" ::: "memory");
        }
        __syncthreads();
        compute(c & 1);
        __syncthreads();
    }

    // ---- stage tile to SMEM (reuse pipeline buffers; 128 x 132 floats) ----
    float* Dsm = reinterpret_cast<float*>(sm);
    #pragma unroll
    for (int mt = 0; mt < 4; mt++) {
        int r = wm * 64 + mt * 16 + gid;
        #pragma unroll
        for (int nt = 0; nt < 4; nt++) {
            int c = wn * 32 + nt * 8 + tig * 2;
            *reinterpret_cast<float2*>(Dsm + r * 132 + c) =
                make_float2(acc[mt][nt][0], acc[mt][nt][1]);
            *reinterpret_cast<float2*>(Dsm + (r + 8) * 132 + c) =
                make_float2(acc[mt][nt][2], acc[mt][nt][3]);
        }
    }
    __syncthreads();

    // ---- edge scatter from SMEM ----
    constexpr int TPE = H / 4;
    constexpr int NSUB = 256 / TPE;
    const int sub = tid / TPE, q = tid % TPE;
    const int end_src = (m0 + 128 <= nrows) ? 128 : (nrows - m0);
    const int r_base = n0 / H;

    auto process = [&](const int* off, const int2* sd, const float* sc, float* outp) {
        #pragma unroll
        for (int ri = 0; ri < 128 / H; ri++) {
            int r = r_base + ri;
            if (r >= RR) break;
            int kb = r * NN + m0;
            int b0 = off[kb], b1 = off[kb + end_src];
            for (int e = b0 + sub; e < b1; e += NSUB) {
                int2 sdv = sd[e];
                float scale = sc[e];
                const float* p = Dsm + (sdv.x - m0) * 132 + ri * H + q * 4;
                float4 v = *reinterpret_cast<const float4*>(p);
                float4 w = make_float4(v.x * scale, v.y * scale, v.z * scale, v.w * scale);
                atomicAdd(reinterpret_cast<float4*>(outp + (size_t)sdv.y * H + q * 4), w);
            }
        }
    };
    process(off0, sd0, sc0, out0);
    if (out1) process(off1, sd1, sc1, out1);
}

// ---------------- CSR build ----------------------------------------------------
__global__ void zero_k() {
    int i = blockIdx.x * blockDim.x + threadIdx.x;
    if (i < KEYS) { g_cnt0[i] = 0; g_cnt1[i] = 0; g_hist0[i] = 0; g_hist1[i] = 0; }
    if (i < HH2) g_colsum[i] = 0.f;
}
__global__ void count_k(const int* __restrict__ ei, const int* __restrict__ et0,
                        const int* __restrict__ et1) {
    int e = blockIdx.x * blockDim.x + threadIdx.x;
    if (e >= EE) return;
    int s = ei[e], d = ei[EE + e];
    int r0 = et0[e], r1 = et1[e];
    atomicAdd(&g_cnt0[r0 * NN + d], 1);
    atomicAdd(&g_cnt1[r1 * NN + d], 1);
    atomicAdd(&g_hist0[r0 * NN + s], 1);
    atomicAdd(&g_hist1[r1 * NN + s], 1);
}
__global__ void inv_k() {
    int i = blockIdx.x * blockDim.x + threadIdx.x;
    if (i >= KEYS) return;
    g_inv0[i] = 1.f / (float)max(g_cnt0[i], 1);
    g_inv1[i] = 1.f / (float)max(g_cnt1[i], 1);
}
__global__ void scan1_k(const int* __restrict__ hist, int* __restrict__ off,
                        int* __restrict__ blk) {
    __shared__ int smi[1024];
    int g = blockIdx.x * 1024 + threadIdx.x;
    int v = (g < KEYS) ? hist[g] : 0;
    smi[threadIdx.x] = v;
    __syncthreads();
    for (int o = 1; o < 1024; o <<= 1) {
        int t = (threadIdx.x >= o) ? smi[threadIdx.x - o] : 0;
        __syncthreads();
        smi[threadIdx.x] += t;
        __syncthreads();
    }
    if (g < KEYS) off[g] = smi[threadIdx.x] - v;
    if (threadIdx.x == 1023) blk[blockIdx.x] = smi[1023];
}
__global__ void scan2_k(int* __restrict__ blk) {
    __shared__ int smi[1024];
    __shared__ int run;
    if (threadIdx.x == 0) run = 0;
    __syncthreads();
    for (int base = 0; base < NBLK; base += 1024) {
        int i = base + threadIdx.x;
        int v = (i < NBLK) ? blk[i] : 0;
        smi[threadIdx.x] = v;
        __syncthreads();
        for (int o = 1; o < 1024; o <<= 1) {
            int t = (threadIdx.x >= o) ? smi[threadIdx.x - o] : 0;
            __syncthreads();
            smi[threadIdx.x] += t;
            __syncthreads();
        }
        int r = run;
        int excl = smi[threadIdx.x] - v + r;
        if (i < NBLK) blk[i] = excl;
        __syncthreads();
        if (threadIdx.x == 1023) run = r + smi[1023];
        __syncthreads();
    }
}
__global__ void scan3_k(int* __restrict__ off, const int* __restrict__ blk,
                        int* __restrict__ cur) {
    int g = blockIdx.x * 1024 + threadIdx.x;
    if (g < KEYS) {
        int v = off[g] + blk[blockIdx.x];
        off[g] = v;
        cur[g] = v;
    }
    if (g == 0) off[KEYS] = EE;
}
__global__ void fill_k(const int* __restrict__ ei, const int* __restrict__ et0,
                       const int* __restrict__ et1) {
    int e = blockIdx.x * blockDim.x + threadIdx.x;
    if (e >= EE) return;
    int s = ei[e], d = ei[EE + e];
    {
        int r = et0[e];
        int p = atomicAdd(&g_cur0[r * NN + s], 1);
        g_sd0[p] = make_int2(s, d);
        g_sc0[p] = g_inv0[r * NN + d];
    }
    {
        int r = et1[e];
        int p = atomicAdd(&g_cur1[r * NN + s], 1);
        g_sd1[p] = make_int2(s, d);
        g_sc1[p] = g_inv1[r * NN + d];
    }
}

// ---------------- conversion kernels -------------------------------------------
__global__ void convX_k(const float* __restrict__ X, __nv_bfloat16* __restrict__ hi,
                        __nv_bfloat16* __restrict__ lo, int n) {
    int i = blockIdx.x * blockDim.x + threadIdx.x;
    if (i >= n) return;
    float v = X[i];
    __nv_bfloat16 h = __float2bfloat16_rn(v);
    hi[i] = h;
    lo[i] = __float2bfloat16_rn(v - __bfloat162float(h));
}
template<int K, int H>
__global__ void convW_k(const float* __restrict__ W, __nv_bfloat16* __restrict__ hi,
                        __nv_bfloat16* __restrict__ lo, int rcols) {
    int i = blockIdx.x * blockDim.x + threadIdx.x;
    if (i >= rcols * K) return;
    int c = i / K, k = i % K;
    float v = W[(size_t)(c / H) * (K * H) + (size_t)k * H + (c % H)];
    __nv_bfloat16 h = __float2bfloat16_rn(v);
    hi[i] = h;
    lo[i] = __float2bfloat16_rn(v - __bfloat162float(h));
}
__global__ void relu_conv_k() {
    int i = blockIdx.x * blockDim.x + threadIdx.x;
    if (i >= NN * HH1) return;
    float a = fmaxf(g_h1O[i], 0.f);  g_h1O[i] = a;
    __nv_bfloat16 h = __float2bfloat16_rn(a);
    g_h1Ohi[i] = h;  g_h1Olo[i] = __float2bfloat16_rn(a - __bfloat162float(h));
    float b = fmaxf(g_h1A[i], 0.f);  g_h1A[i] = b;
    h = __float2bfloat16_rn(b);
    g_h1Ahi[i] = h;  g_h1Alo[i] = __float2bfloat16_rn(b - __bfloat162float(h));
    float c = fmaxf(g_h1Aa[i], 0.f); g_h1Aa[i] = c;
    h = __float2bfloat16_rn(c);
    g_h1Aahi[i] = h; g_h1Aalo[i] = __float2bfloat16_rn(c - __bfloat162float(h));
}

// ---------------- root GEMM (SIMT, small) --------------------------------------
template<int K, int H>
__global__ void __launch_bounds__((H/4)*16)
gemm_rel(const float* __restrict__ X, const float* __restrict__ Wm,
         const float* __restrict__ bias, float* __restrict__ Y,
         float* __restrict__ Ydup, int ldY, int nrows)
{
    constexpr int TM = 64, KC = 64;
    constexpr int DX = H / 4;
    constexpr int NT = DX * 16;
    __shared__ __align__(16) float At[KC][TM + 4];
    __shared__ __align__(16) float Bs[KC][H];
    int row0 = blockIdx.x * TM;
    int tx = threadIdx.x, ty = threadIdx.y;
    int tid = ty * DX + tx;
    int c0 = tx * 4, r0 = ty * 4;
    float acc[4][4] = {};
    for (int kc = 0; kc < K; kc += KC) {
        for (int c = tid; c < TM * (KC / 4); c += NT) {
            int row = c / (KC / 4), kq = c % (KC / 4);
            float4 v = make_float4(0.f, 0.f, 0.f, 0.f);
            if (row0 + row < nrows)
                v = *reinterpret_cast<const float4*>(X + (size_t)(row0 + row) * K + kc + kq * 4);
            At[kq * 4 + 0][row] = v.x; At[kq * 4 + 1][row] = v.y;
            At[kq * 4 + 2][row] = v.z; At[kq * 4 + 3][row] = v.w;
        }
        for (int c = tid; c < KC * H / 4; c += NT)
            reinterpret_cast<float4*>(&Bs[0][0])[c] =
                reinterpret_cast<const float4*>(Wm + (size_t)kc * H)[c];
        __syncthreads();
        #pragma unroll 8
        for (int k = 0; k < KC; k++) {
            float4 a = *reinterpret_cast<const float4*>(&At[k][r0]);
            float4 b = *reinterpret_cast<const float4*>(&Bs[k][c0]);
            acc[0][0] += a.x*b.x; acc[0][1] += a.x*b.y; acc[0][2] += a.x*b.z; acc[0][3] += a.x*b.w;
            acc[1][0] += a.y*b.x; acc[1][1] += a.y*b.y; acc[1][2] += a.y*b.z; acc[1][3] += a.y*b.w;
            acc[2][0] += a.z*b.x; acc[2][1] += a.z*b.y; acc[2][2] += a.z*b.z; acc[2][3] += a.z*b.w;
            acc[3][0] += a.w*b.x; acc[3][1] += a.w*b.y; acc[3][2] += a.w*b.z; acc[3][3] += a.w*b.w;
        }
        __syncthreads();
    }
    float4 bv = make_float4(0.f, 0.f, 0.f, 0.f);
    if (bias) bv = *reinterpret_cast<const float4*>(bias + c0);
    #pragma unroll
    for (int i = 0; i < 4; i++) {
        int row = row0 + r0 + i;
        if (row < nrows) {
            float4 o = make_float4(acc[i][0] + bv.x, acc[i][1] + bv.y,
                                   acc[i][2] + bv.z, acc[i][3] + bv.w);
            *reinterpret_cast<float4*>(Y + (size_t)row * ldY + c0) = o;
            if (Ydup) *reinterpret_cast<float4*>(Ydup + (size_t)row * ldY + c0) = o;
        }
    }
}

// ---------------- readout / discriminator --------------------------------------
__global__ void colsum_k() {
    __shared__ float smf[256];
    int col = threadIdx.x & 31, grp = threadIdx.x >> 5;
    float s = 0.f;
    for (int n = blockIdx.x * 8 + grp; n < NN; n += gridDim.x * 8)
        s += g_x2o[n * HH2 + col];
    smf[threadIdx.x] = s;
    __syncthreads();
    if (threadIdx.x < 32) {
        float t = 0.f;
        #pragma unroll
        for (int g2 = 0; g2 < 8; g2++) t += smf[g2 * 32 + threadIdx.x];
        atomicAdd(&g_colsum[threadIdx.x], t);
    }
}
__global__ void finalize_k(const float* __restrict__ discW) {
    __shared__ float c[HH2];
    int t = threadIdx.x;
    float m = g_colsum[t] / (float)NN;
    c[t] = 1.f / (1.f + expf(-m));
    __syncwarp();
    float v = 0.f;
    #pragma unroll
    for (int k = 0; k < HH2; k++) v += discW[t * HH2 + k] * c[k];
    g_v[t] = v;
}
__global__ void ret_k(const float* __restrict__ dbp, float* __restrict__ out) {
    int n = blockIdx.x * blockDim.x + threadIdx.x;
    if (n >= NN) return;
    float db = dbp[0];
    float d0 = 0.f, d1 = 0.f, d2 = 0.f;
    float* xo_out = out + OUT_X2O + (size_t)n * HH2;
    #pragma unroll
    for (int k = 0; k < HH2; k += 4) {
        float4 v4 = *reinterpret_cast<const float4*>(&g_v[k]);
        float4 a  = *reinterpret_cast<const float4*>(&g_x2o[n * HH2 + k]);
        float4 b  = *reinterpret_cast<const float4*>(&g_x2oa[n * HH2 + k]);
        float4 c  = *reinterpret_cast<const float4*>(&g_x2oaa[n * HH2 + k]);
        d0 += a.x*v4.x + a.y*v4.y + a.z*v4.z + a.w*v4.w;
        d1 += b.x*v4.x + b.y*v4.y + b.z*v4.z + b.w*v4.w;
        d2 += c.x*v4.x + c.y*v4.y + c.z*v4.z + c.w*v4.w;
        *reinterpret_cast<float4*>(&xo_out[k]) = a;
    }
    out[OUT_RETOS  + 2 * n]     = d0 + db;
    out[OUT_RETOS  + 2 * n + 1] = d1 + db;
    out[OUT_RETOSA + 2 * n]     = d0 + db;
    out[OUT_RETOSA + 2 * n + 1] = d2 + db;
}
__global__ void cls_k(const int* __restrict__ idx, const float* __restrict__ f1,
                      const float* __restrict__ clsW, const float* __restrict__ clsB,
                      const float* __restrict__ attt, float* __restrict__ out)
{
    __shared__ float z[448];
    int b = blockIdx.x, t = threadIdx.x;
    int i0 = idx[b], i1 = idx[BB + b];
    float a0 = attt[0], a1 = attt[1];
    for (int k = t; k < 448; k += 128) {
        float val;
        if      (k < 64)  val = a0 * g_h1O[(size_t)i0 * 64 + k];
        else if (k < 96)  val = a1 * g_x2o[(size_t)i0 * 32 + (k - 64)];
        else if (k < 224) val = f1[(size_t)i0 * 128 + (k - 96)];
        else if (k < 288) val = a0 * g_h1O[(size_t)i1 * 64 + (k - 224)];
        else if (k < 320) val = a1 * g_x2o[(size_t)i1 * 32 + (k - 288)];
        else              val = f1[(size_t)i1 * 128 + (k - 320)];
        z[k] = val;
    }
    __syncthreads();
    if (t < RR) {
        float acc = clsB[t];
        #pragma unroll 4
        for (int k = 0; k < 448; k++) acc += z[k] * clsW[k * RR + t];
        out[(size_t)b * RR + t] = acc;
    }
}

// ---------------- launcher ------------------------------------------------------
extern "C" void kernel_launch(void* const* d_in, const int* in_sizes, int n_in,
                              void* d_out, int out_size)
{
    (void)in_sizes; (void)n_in; (void)out_size;
    const float* x_o   = (const float*)d_in[0];
    const float* x_a   = (const float*)d_in[1];
    const float* f1    = (const float*)d_in[2];
    const float* W1    = (const float*)d_in[3];
    const float* root1 = (const float*)d_in[4];
    const float* b1    = (const float*)d_in[5];
    const float* W2    = (const float*)d_in[6];
    const float* root2 = (const float*)d_in[7];
    const float* b2    = (const float*)d_in[8];
    const float* attt  = (const float*)d_in[9];
    const float* discW = (const float*)d_in[10];
    const float* discb = (const float*)d_in[11];
    const float* clsW  = (const float*)d_in[12];
    const float* clsb  = (const float*)d_in[13];
    const int*   ei    = (const int*)d_in[14];
    const int*   et0   = (const int*)d_in[15];
    const int*   et1   = (const int*)d_in[16];
    const int*   idx   = (const int*)d_in[17];
    float* out = (float*)d_out;

    float *h1O, *h1A, *h1Aa, *x2o, *x2oa, *x2oaa;
    cudaGetSymbolAddress((void**)&h1O,   g_h1O);
    cudaGetSymbolAddress((void**)&h1A,   g_h1A);
    cudaGetSymbolAddress((void**)&h1Aa,  g_h1Aa);
    cudaGetSymbolAddress((void**)&x2o,   g_x2o);
    cudaGetSymbolAddress((void**)&x2oa,  g_x2oa);
    cudaGetSymbolAddress((void**)&x2oaa, g_x2oaa);

    int *off0, *off1, *cur0, *cur1, *hist0, *hist1, *blk0, *blk1;
    int2 *sd0, *sd1;
    float *sc0, *sc1;
    cudaGetSymbolAddress((void**)&off0, g_off0);   cudaGetSymbolAddress((void**)&off1, g_off1);
    cudaGetSymbolAddress((void**)&cur0, g_cur0);   cudaGetSymbolAddress((void**)&cur1, g_cur1);
    cudaGetSymbolAddress((void**)&hist0, g_hist0); cudaGetSymbolAddress((void**)&hist1, g_hist1);
    cudaGetSymbolAddress((void**)&blk0, g_blk0);   cudaGetSymbolAddress((void**)&blk1, g_blk1);
    cudaGetSymbolAddress((void**)&sd0, g_sd0);     cudaGetSymbolAddress((void**)&sd1, g_sd1);
    cudaGetSymbolAddress((void**)&sc0, g_sc0);     cudaGetSymbolAddress((void**)&sc1, g_sc1);

    __nv_bfloat16 *xohi,*xolo,*xahi,*xalo,*w1hi,*w1lo,*w2hi,*w2lo;
    __nv_bfloat16 *h1Ohi,*h1Olo,*h1Ahi,*h1Alo,*h1Aahi,*h1Aalo;
    cudaGetSymbolAddress((void**)&xohi, g_xohi);   cudaGetSymbolAddress((void**)&xolo, g_xolo);
    cudaGetSymbolAddress((void**)&xahi, g_xahi);   cudaGetSymbolAddress((void**)&xalo, g_xalo);
    cudaGetSymbolAddress((void**)&w1hi, g_w1hi);   cudaGetSymbolAddress((void**)&w1lo, g_w1lo);
    cudaGetSymbolAddress((void**)&w2hi, g_w2hi);   cudaGetSymbolAddress((void**)&w2lo, g_w2lo);
    cudaGetSymbolAddress((void**)&h1Ohi, g_h1Ohi); cudaGetSymbolAddress((void**)&h1Olo, g_h1Olo);
    cudaGetSymbolAddress((void**)&h1Ahi, g_h1Ahi); cudaGetSymbolAddress((void**)&h1Alo, g_h1Alo);
    cudaGetSymbolAddress((void**)&h1Aahi, g_h1Aahi); cudaGetSymbolAddress((void**)&h1Aalo, g_h1Aalo);

    const int SMP = 2 * 4 * 128 * 40 * 2;   // 81920 (>= 67584 Dsm)
    cudaFuncSetAttribute(gemm_fused<FIN, HH1, RCOLS1>,
                         cudaFuncAttributeMaxDynamicSharedMemorySize, SMP);
    cudaFuncSetAttribute(gemm_fused<HH1, HH2, RCOLS2>,
                         cudaFuncAttributeMaxDynamicSharedMemorySize, SMP);

    const int tK = (KEYS + 255) / 256;
    const int gx = (NN + 63) / 64;
    const int gm = (NN + 127) / 128;
    dim3 g1(gm, (RCOLS1 + 127) / 128);
    dim3 g2(gm, (RCOLS2 + 127) / 128);
    dim3 gb1(16, 16), gb2(8, 16);

    // ---- CSR build + conversions ----
    zero_k<<<tK, 256>>>();
    count_k<<<(EE + 255) / 256, 256>>>(ei, et0, et1);
    inv_k<<<tK, 256>>>();
    scan1_k<<<NBLK, 1024>>>(hist0, off0, blk0);
    scan1_k<<<NBLK, 1024>>>(hist1, off1, blk1);
    scan2_k<<<1, 1024>>>(blk0);
    scan2_k<<<1, 1024>>>(blk1);
    scan3_k<<<NBLK, 1024>>>(off0, blk0, cur0);
    scan3_k<<<NBLK, 1024>>>(off1, blk1, cur1);
    fill_k<<<(EE + 255) / 256, 256>>>(ei, et0, et1);

    convX_k<<<(NN * FIN + 255) / 256, 256>>>(x_o, xohi, xolo, NN * FIN);
    convX_k<<<(NN * FIN + 255) / 256, 256>>>(x_a, xahi, xalo, NN * FIN);
    convW_k<FIN, HH1><<<(RCOLS1 * FIN + 255) / 256, 256>>>(W1, w1hi, w1lo, RCOLS1);
    convW_k<HH1, HH2><<<(RCOLS2 * HH1 + 255) / 256, 256>>>(W2, w2hi, w2lo, RCOLS2);

    // ---- layer 1: root inits (write), then fused GEMM+scatter (RED) ----
    gemm_rel<FIN, HH1><<<gx, gb1>>>(x_o, root1, b1, h1O, h1Aa, HH1, NN);
    gemm_rel<FIN, HH1><<<gx, gb1>>>(x_a, root1, b1, h1A, nullptr, HH1, NN);
    gemm_fused<FIN, HH1, RCOLS1><<<g1, 256, SMP>>>(
        xohi, xolo, w1hi, w1lo,
        off0, sd0, sc0, h1O, off1, sd1, sc1, h1Aa, NN);
    gemm_fused<FIN, HH1, RCOLS1><<<g1, 256, SMP>>>(
        xahi, xalo, w1hi, w1lo,
        off0, sd0, sc0, h1A, nullptr, nullptr, nullptr, nullptr, NN);

    relu_conv_k<<<(NN * HH1 + 255) / 256, 256>>>();

    // ---- layer 2: root inits, then fused GEMM+scatter ----
    gemm_rel<HH1, HH2><<<gx, gb2>>>(h1O, root2, b2, x2o, nullptr, HH2, NN);
    gemm_rel<HH1, HH2><<<gx, gb2>>>(h1A, root2, b2, x2oa, nullptr, HH2, NN);
    gemm_rel<HH1, HH2><<<gx, gb2>>>(h1Aa, root2, b2, x2oaa, nullptr, HH2, NN);
    gemm_fused<HH1, HH2, RCOLS2><<<g2, 256, SMP>>>(
        h1Ohi, h1Olo, w2hi, w2lo,
        off0, sd0, sc0, x2o, nullptr, nullptr, nullptr, nullptr, NN);
    gemm_fused<HH1, HH2, RCOLS2><<<g2, 256, SMP>>>(
        h1Ahi, h1Alo, w2hi, w2lo,
        off0, sd0, sc0, x2oa, nullptr, nullptr, nullptr, nullptr, NN);
    gemm_fused<HH1, HH2, RCOLS2><<<g2, 256, SMP>>>(
        h1Aahi, h1Aalo, w2hi, w2lo,
        off1, sd1, sc1, x2oaa, nullptr, nullptr, nullptr, nullptr, NN);

    // ---- readout / outputs ----
    colsum_k<<<80, 256>>>();
    finalize_k<<<1, 32>>>(discW);
    ret_k<<<(NN + 127) / 128, 128>>>(discb, out);
    cls_k<<<BB, 128>>>(idx, f1, clsW, clsb, attt, out);
}